// round 2
// baseline (speedup 1.0000x reference)
#include <cuda_runtime.h>
#include <cstdint>

// out[n,o,s] = sum_{c,k} din[n,c,s,k] * W[o,c,k] + b[o]
// din[n,c,s,0]=x[n,c,2s], din[n,c,s,1]=x[n,c,2s+1], din[n,c,s,2]=d[n,c,s]
// x:[N,32,12] d:[N,32,6] W:[32,32,3] b:[32] out:[N,32,6] fp32, N=131072
//
// k-order permutation m (0..95):
//   m < 64:  m = 2c+q (q in {0,1})  -> kk = 3c+q   (the two x taps)
//   m >= 64: m = 64+c               -> kk = 3c+2   (the d tap)
// Column pairs: j = 2*jp + e, j = 6*i + s (sample i, slot s).
// Smem: VsX[jp][4c + 2q + e]  (x part, stride 132 words, LDS.128-friendly)
//       VsD[jp][2c + e]       (d part, stride 66 words, LDS.64-friendly)
// W duplicated: WD_g[m*64 + 2o + {0,1}] = W[o][kk(m)]  -> natural f32x2 operand.

#define TBS 32
#define NJP 96            // column pairs per block = TBS*6/2
#define XSTRIDE 132       // 64 m * 2 + 4 pad (stride/4 = 33, odd -> conflict-free LDS.128)
#define DSTRIDE 66        // 32 m * 2 + 2 pad (stride/2 = 33, odd -> conflict-free LDS.64)
#define XWORDS (NJP * XSTRIDE)
#define SMEM_BYTES (NJP * (XSTRIDE + DSTRIDE) * 4)   // 76032 B

__device__ __align__(16) float WD_g[96 * 64];

__global__ void prep_WD(const float* __restrict__ W) {
    int t = blockIdx.x * blockDim.x + threadIdx.x;
    if (t < 96 * 32) {
        int m = t >> 5, o = t & 31;
        int kk = (m < 64) ? (3 * (m >> 1) + (m & 1)) : (3 * (m - 64) + 2);
        float v = W[o * 96 + kk];
        WD_g[m * 64 + 2 * o]     = v;
        WD_g[m * 64 + 2 * o + 1] = v;
    }
}

__global__ void __launch_bounds__(128)
dijet_kernel(const float* __restrict__ x, const float* __restrict__ d,
             const float* __restrict__ b, float* __restrict__ out, int n)
{
    extern __shared__ float smem[];
    float* VsX = smem;
    float* VsD = smem + XWORDS;

    const int tid  = threadIdx.x;
    const int n0   = blockIdx.x * TBS;
    const int nloc = min(n - n0, TBS);

    // ---- stage x: coalesced LDG.128, aligned STS.128 ----
    // float4 t: sample i = t/96, rem = c*3 + q. Elements (pos 4q..4q+3) map to
    // words [4c..4c+3] of row jp = 3i+q with component order {x, z, y, w}.
    {
        const float4* x4 = reinterpret_cast<const float4*>(x) + (size_t)n0 * 96;
        const int lim = nloc * 96;
        for (int t = tid; t < lim; t += 128) {
            float4 v = x4[t];
            int i = t / 96, rem = t - i * 96;
            int c = rem / 3, q = rem - c * 3;
            float4 sv = make_float4(v.x, v.z, v.y, v.w);
            *reinterpret_cast<float4*>(VsX + (3 * i + q) * XSTRIDE + 4 * c) = sv;
        }
    }
    // ---- stage d: coalesced LDG.128, two aligned STS.64 per float4 ----
    {
        const float4* d4 = reinterpret_cast<const float4*>(d) + (size_t)n0 * 48;
        const int lim = nloc * 48;
        for (int t = tid; t < lim; t += 128) {
            float4 v = d4[t];
            int i = t / 48, rem = t - i * 48;
            int ff = 4 * rem;                 // even -> s-pairs stay intact
            int c0 = ff / 6,       s0 = ff - 6 * c0;
            int c2 = (ff + 2) / 6, s2 = (ff + 2) - 6 * c2;
            *reinterpret_cast<float2*>(VsD + (3 * i + (s0 >> 1)) * DSTRIDE + 2 * c0) =
                make_float2(v.x, v.y);
            *reinterpret_cast<float2*>(VsD + (3 * i + (s2 >> 1)) * DSTRIDE + 2 * c2) =
                make_float2(v.z, v.w);
        }
    }
    __syncthreads();

    // ---- compute: warp = 8 rows (o0..o0+7), lane = 3 column pairs jp = cg + 32*pp ----
    const int wid = tid >> 5, cg = tid & 31;
    const int o0 = wid * 8;

    int jp[3], ii[3], sp[3];
    #pragma unroll
    for (int pp = 0; pp < 3; pp++) {
        jp[pp] = cg + 32 * pp;
        ii[pp] = jp[pp] / 3;
        sp[pp] = jp[pp] - 3 * ii[pp];
    }

    unsigned long long acc[8][3];
    #pragma unroll
    for (int r = 0; r < 8; r++) {
        float bv = b[o0 + r];
        unsigned long long bp;
        asm("mov.b64 %0, {%1, %1};" : "=l"(bp) : "r"(__float_as_uint(bv)));
        acc[r][0] = bp; acc[r][1] = bp; acc[r][2] = bp;
    }

    const float* wbase = WD_g + 2 * o0;    // row-dup pairs for this warp, + m*64

    // ---- x-part: 32 iterations, each covers m = 2mm, 2mm+1 ----
    #pragma unroll 2
    for (int mm = 0; mm < 32; mm++) {
        unsigned long long wm0[8], wm1[8];
        #pragma unroll
        for (int h = 0; h < 4; h++) {
            ulonglong2 a0 = *reinterpret_cast<const ulonglong2*>(wbase + (2 * mm) * 64 + 4 * h);
            wm0[2 * h] = a0.x; wm0[2 * h + 1] = a0.y;
            ulonglong2 a1 = *reinterpret_cast<const ulonglong2*>(wbase + (2 * mm + 1) * 64 + 4 * h);
            wm1[2 * h] = a1.x; wm1[2 * h + 1] = a1.y;
        }
        #pragma unroll
        for (int pp = 0; pp < 3; pp++) {
            ulonglong2 vv = *reinterpret_cast<const ulonglong2*>(VsX + jp[pp] * XSTRIDE + 4 * mm);
            #pragma unroll
            for (int r = 0; r < 8; r++) {
                asm("fma.rn.f32x2 %0, %1, %2, %0;" : "+l"(acc[r][pp]) : "l"(wm0[r]), "l"(vv.x));
                asm("fma.rn.f32x2 %0, %1, %2, %0;" : "+l"(acc[r][pp]) : "l"(wm1[r]), "l"(vv.y));
            }
        }
    }

    // ---- d-part: 32 iterations, one m each ----
    #pragma unroll 2
    for (int md = 0; md < 32; md++) {
        unsigned long long wm[8];
        #pragma unroll
        for (int h = 0; h < 4; h++) {
            ulonglong2 a = *reinterpret_cast<const ulonglong2*>(wbase + (64 + md) * 64 + 4 * h);
            wm[2 * h] = a.x; wm[2 * h + 1] = a.y;
        }
        #pragma unroll
        for (int pp = 0; pp < 3; pp++) {
            unsigned long long vv =
                *reinterpret_cast<const unsigned long long*>(VsD + jp[pp] * DSTRIDE + 2 * md);
            #pragma unroll
            for (int r = 0; r < 8; r++)
                asm("fma.rn.f32x2 %0, %1, %2, %0;" : "+l"(acc[r][pp]) : "l"(wm[r]), "l"(vv));
        }
    }

    // ---- store: STG.64 per (row, column-pair) ----
    #pragma unroll
    for (int pp = 0; pp < 3; pp++) {
        if (ii[pp] < nloc) {
            float* op = out + ((size_t)(n0 + ii[pp]) * 32 + o0) * 6 + 2 * sp[pp];
            #pragma unroll
            for (int r = 0; r < 8; r++)
                *reinterpret_cast<unsigned long long*>(op + r * 6) = acc[r][pp];
        }
    }
}

extern "C" void kernel_launch(void* const* d_in, const int* in_sizes, int n_in,
                              void* d_out, int out_size) {
    const float* x = (const float*)d_in[0];
    const float* d = (const float*)d_in[1];
    const float* W = (const float*)d_in[2];
    const float* b = (const float*)d_in[3];
    float* out = (float*)d_out;

    int n = in_sizes[0] / 384;

    cudaFuncSetAttribute(dijet_kernel, cudaFuncAttributeMaxDynamicSharedMemorySize, SMEM_BYTES);
    prep_WD<<<12, 256>>>(W);
    dijet_kernel<<<(n + TBS - 1) / TBS, 128, SMEM_BYTES>>>(x, d, b, out, n);
}

// round 4
// speedup vs baseline: 1.0115x; 1.0115x over previous
#include <cuda_runtime.h>
#include <cstdint>

// out[n,o,s] = sum_{c,k} din[n,c,s,k] * W[o,c,k] + b[o]
// din[n,c,s,0]=x[n,c,2s], din[n,c,s,1]=x[n,c,2s+1], din[n,c,s,2]=d[n,c,s]
// x:[N,32,12] d:[N,32,6] W:[32,32,3] b:[32] out:[N,32,6] fp32, N=131072
//
// k-order permutation m (0..95):
//   m < 64:  m = 2c+q (q in {0,1})  -> kk = 3c+q   (the two x taps)
//   m >= 64: m = 64+c               -> kk = 3c+2   (the d tap)
// Column pairs: j = 2*jp + e, j = 6*i + s (sample i, slot s).
// Smem: VsX[jp][4c + 2q + e]  (x part, stride 132 words, LDS.128-friendly)
//       VsD[jp][2c + e]       (d part, stride 66 words, LDS.64-friendly)
// W duplicated: WD_g[m*64 + 2o + {0,1}] = W[o][kk(m)]  -> natural f32x2 operand.

#define TBS 32
#define NJP 96            // column pairs per block = TBS*6/2
#define XSTRIDE 132       // 64 m * 2 + 4 pad (stride/4 = 33, odd -> conflict-free LDS.128)
#define DSTRIDE 66        // 32 m * 2 + 2 pad (stride/2 = 33, odd -> conflict-free LDS.64)
#define XWORDS (NJP * XSTRIDE)
#define SMEM_BYTES (NJP * (XSTRIDE + DSTRIDE) * 4)   // 76032 B

__device__ __align__(16) float WD_g[96 * 64];

__global__ void prep_WD(const float* __restrict__ W) {
    int t = blockIdx.x * blockDim.x + threadIdx.x;
    if (t < 96 * 32) {
        int m = t >> 5, o = t & 31;
        int kk = (m < 64) ? (3 * (m >> 1) + (m & 1)) : (3 * (m - 64) + 2);
        float v = W[o * 96 + kk];
        WD_g[m * 64 + 2 * o]     = v;
        WD_g[m * 64 + 2 * o + 1] = v;
    }
}

__global__ void __launch_bounds__(128)
dijet_kernel(const float* __restrict__ x, const float* __restrict__ d,
             const float* __restrict__ b, float* __restrict__ out, int n)
{
    extern __shared__ float smem[];
    float* VsX = smem;
    float* VsD = smem + XWORDS;

    const int tid  = threadIdx.x;
    const int n0   = blockIdx.x * TBS;
    const int nloc = min(n - n0, TBS);

    // ---- stage x: coalesced LDG.128, aligned STS.128 ----
    // float4 t: sample i = t/96, rem = c*3 + q. Elements (pos 4q..4q+3) map to
    // words [4c..4c+3] of row jp = 3i+q with component order {x, z, y, w}.
    {
        const float4* x4 = reinterpret_cast<const float4*>(x) + (size_t)n0 * 96;
        const int lim = nloc * 96;
        for (int t = tid; t < lim; t += 128) {
            float4 v = x4[t];
            int i = t / 96, rem = t - i * 96;
            int c = rem / 3, q = rem - c * 3;
            float4 sv = make_float4(v.x, v.z, v.y, v.w);
            *reinterpret_cast<float4*>(VsX + (3 * i + q) * XSTRIDE + 4 * c) = sv;
        }
    }
    // ---- stage d: coalesced LDG.128, two aligned STS.64 per float4 ----
    {
        const float4* d4 = reinterpret_cast<const float4*>(d) + (size_t)n0 * 48;
        const int lim = nloc * 48;
        for (int t = tid; t < lim; t += 128) {
            float4 v = d4[t];
            int i = t / 48, rem = t - i * 48;
            int ff = 4 * rem;                 // even -> s-pairs stay intact
            int c0 = ff / 6,       s0 = ff - 6 * c0;
            int c2 = (ff + 2) / 6, s2 = (ff + 2) - 6 * c2;
            *reinterpret_cast<float2*>(VsD + (3 * i + (s0 >> 1)) * DSTRIDE + 2 * c0) =
                make_float2(v.x, v.y);
            *reinterpret_cast<float2*>(VsD + (3 * i + (s2 >> 1)) * DSTRIDE + 2 * c2) =
                make_float2(v.z, v.w);
        }
    }
    __syncthreads();

    // ---- compute: warp = 8 rows (o0..o0+7), lane = 3 column pairs jp = cg + 32*pp ----
    const int wid = tid >> 5, cg = tid & 31;
    const int o0 = wid * 8;

    int jp[3], ii[3], sp[3];
    #pragma unroll
    for (int pp = 0; pp < 3; pp++) {
        jp[pp] = cg + 32 * pp;
        ii[pp] = jp[pp] / 3;
        sp[pp] = jp[pp] - 3 * ii[pp];
    }

    unsigned long long acc[8][3];
    #pragma unroll
    for (int r = 0; r < 8; r++) {
        float bv = b[o0 + r];
        unsigned long long bp;
        asm("mov.b64 %0, {%1, %1};" : "=l"(bp) : "r"(__float_as_uint(bv)));
        acc[r][0] = bp; acc[r][1] = bp; acc[r][2] = bp;
    }

    const float* wbase = WD_g + 2 * o0;    // row-dup pairs for this warp, + m*64

    // ---- x-part: 32 iterations, each covers m = 2mm, 2mm+1 ----
    #pragma unroll 2
    for (int mm = 0; mm < 32; mm++) {
        unsigned long long wm0[8], wm1[8];
        #pragma unroll
        for (int h = 0; h < 4; h++) {
            ulonglong2 a0 = *reinterpret_cast<const ulonglong2*>(wbase + (2 * mm) * 64 + 4 * h);
            wm0[2 * h] = a0.x; wm0[2 * h + 1] = a0.y;
            ulonglong2 a1 = *reinterpret_cast<const ulonglong2*>(wbase + (2 * mm + 1) * 64 + 4 * h);
            wm1[2 * h] = a1.x; wm1[2 * h + 1] = a1.y;
        }
        #pragma unroll
        for (int pp = 0; pp < 3; pp++) {
            ulonglong2 vv = *reinterpret_cast<const ulonglong2*>(VsX + jp[pp] * XSTRIDE + 4 * mm);
            #pragma unroll
            for (int r = 0; r < 8; r++) {
                asm("fma.rn.f32x2 %0, %1, %2, %0;" : "+l"(acc[r][pp]) : "l"(wm0[r]), "l"(vv.x));
                asm("fma.rn.f32x2 %0, %1, %2, %0;" : "+l"(acc[r][pp]) : "l"(wm1[r]), "l"(vv.y));
            }
        }
    }

    // ---- d-part: 32 iterations, one m each ----
    #pragma unroll 2
    for (int md = 0; md < 32; md++) {
        unsigned long long wm[8];
        #pragma unroll
        for (int h = 0; h < 4; h++) {
            ulonglong2 a = *reinterpret_cast<const ulonglong2*>(wbase + (64 + md) * 64 + 4 * h);
            wm[2 * h] = a.x; wm[2 * h + 1] = a.y;
        }
        #pragma unroll
        for (int pp = 0; pp < 3; pp++) {
            unsigned long long vv =
                *reinterpret_cast<const unsigned long long*>(VsD + jp[pp] * DSTRIDE + 2 * md);
            #pragma unroll
            for (int r = 0; r < 8; r++)
                asm("fma.rn.f32x2 %0, %1, %2, %0;" : "+l"(acc[r][pp]) : "l"(wm[r]), "l"(vv));
        }
    }

    // ---- store: STG.64 per (row, column-pair) ----
    #pragma unroll
    for (int pp = 0; pp < 3; pp++) {
        if (ii[pp] < nloc) {
            float* op = out + ((size_t)(n0 + ii[pp]) * 32 + o0) * 6 + 2 * sp[pp];
            #pragma unroll
            for (int r = 0; r < 8; r++)
                *reinterpret_cast<unsigned long long*>(op + r * 6) = acc[r][pp];
        }
    }
}

extern "C" void kernel_launch(void* const* d_in, const int* in_sizes, int n_in,
                              void* d_out, int out_size) {
    const float* x = (const float*)d_in[0];
    const float* d = (const float*)d_in[1];
    const float* W = (const float*)d_in[2];
    const float* b = (const float*)d_in[3];
    float* out = (float*)d_out;

    int n = in_sizes[0] / 384;

    cudaFuncSetAttribute(dijet_kernel, cudaFuncAttributeMaxDynamicSharedMemorySize, SMEM_BYTES);
    prep_WD<<<12, 256>>>(W);
    dijet_kernel<<<(n + TBS - 1) / TBS, 128, SMEM_BYTES>>>(x, d, b, out, n);
}

// round 6
// speedup vs baseline: 2.9757x; 2.9419x over previous
#include <cuda_runtime.h>
#include <cstdint>

// out[n,o,s] = sum_k din[j,k] * W[o,k] + b[o],  j = n*6+s, K=96 (k = 3c+tap)
// din[j,3c+0]=x[n,c,2s], din[j,3c+1]=x[n,c,2s+1], din[j,3c+2]=d[n,c,s]
// GEMM via mma.sync.m16n8k8.row.col.f32.tf32.tf32.f32 (plain PTX, compiles for compute_103).
// A staged in smem directly in fragment order; B (W) pre-packed in fragment order by prep.

#define ROWS 192            // = 32 samples exactly -> no row masking inside blocks
#define THREADS 384         // 12 warps; warp w owns mtile w (16 rows)
#define NKT 12              // K tiles (96/8)
#define NNT 4               // N tiles (32/8)
#define A_OFF 0
#define A_BYTES (ROWS * 96 * 4)            // 73728, fragment-ordered
#define B_OFF A_BYTES
#define B_BYTES (NKT * NNT * 64 * 4)       // 12288
#define BIAS_OFF (B_OFF + B_BYTES)         // 86016
#define SMEM_TOTAL (BIAS_OFF + 128)        // 86144 -> 2 CTAs/SM

// A fragment word offset for logical (row r in [0,192), col w in [0,96)):
//   mtile=r>>4, ktile=w>>3, lane=(r&7)*4+(w&3), reg=((w>>2)&1)*2+((r>>3)&1)
static __host__ __device__ __forceinline__ int a_word(int r, int w) {
    return (r >> 4) * (NKT * 128) + (w >> 3) * 128
         + (r & 7) * 16 + (w & 3) * 4 + ((w >> 2) & 1) * 2 + ((r >> 3) & 1);
}

// W in B-fragment order: block (kt,nt) 64 words; b0=(k=t, o=g), b1=(k=t+4, o=g)
__device__ __align__(16) float WF_g[NKT * NNT * 64];

__global__ void prep_WF(const float* __restrict__ W) {
    int t = blockIdx.x * blockDim.x + threadIdx.x;
    if (t < 3072) {
        int o = t / 96, k = t - 96 * o;
        uint32_t v;
        asm("cvt.rna.tf32.f32 %0, %1;" : "=r"(v) : "f"(W[t]));
        int word = ((k >> 3) * NNT + (o >> 3)) * 64
                 + ((o & 7) * 4 + (k & 3)) * 2 + ((k >> 2) & 1);
        WF_g[word] = __uint_as_float(v);
    }
}

static __device__ __forceinline__ uint32_t smem_u32(const void* p) {
    uint32_t a;
    asm("{ .reg .u64 t; cvta.to.shared.u64 t, %1; cvt.u32.u64 %0, t; }" : "=r"(a) : "l"(p));
    return a;
}
static __device__ __forceinline__ void sts_tf32(int addr, float v) {
    uint32_t t;
    asm("cvt.rna.tf32.f32 %0, %1;" : "=r"(t) : "f"(v));
    asm volatile("st.shared.b32 [%0], %1;" :: "r"(addr), "r"(t));
}

__global__ void __launch_bounds__(THREADS, 2)
dijet_mma(const float* __restrict__ x, const float* __restrict__ dd,
          const float* __restrict__ bvec, float* __restrict__ out, int nsamp)
{
    extern __shared__ char smem[];
    const uint32_t sb = smem_u32(smem);
    const int tid  = threadIdx.x;
    const int j0   = blockIdx.x * ROWS;
    const int n0   = j0 / 6;               // ROWS multiple of 6 -> exact

    // ---- stage B (pre-packed) + bias ----
    {
        const float4* wf4 = (const float4*)WF_g;
        float4* b4 = (float4*)(smem + B_OFF);
        #pragma unroll
        for (int t = tid; t < B_BYTES / 16; t += THREADS) b4[t] = wf4[t];
        if (tid < 32) ((float*)(smem + BIAS_OFF))[tid] = bvec[tid];
    }

    // ---- stage x: thread owns (i0 = tid/96, rem); 8 steps of +4 samples ----
    {
        const int i0  = tid / 96;                    // 0..3
        const int rem = tid - 96 * i0;               // f4 index within sample
        const int c   = rem / 3, qq = rem - 3 * c;
        int addr[4], dlt[4];
        #pragma unroll
        for (int e = 0; e < 4; e++) {
            int pos = 4 * qq + e;                    // 0..11 within x row
            int s = pos >> 1, par = pos & 1;
            int w = 3 * c + par;
            int r = 6 * i0 + s;
            addr[e] = (int)sb + A_OFF + 4 * a_word(r, w);
            dlt[e]  = ((r >> 3) & 1) ? 12284 : 6148; // r += 24 alternates these
        }
        const float4* x4 = (const float4*)x;
        int g = (n0 + i0) * 96 + rem;
        int n = n0 + i0;
        #pragma unroll
        for (int st = 0; st < 8; st++) {
            if (n < nsamp) {
                float4 v = x4[g];
                sts_tf32(addr[0], v.x); sts_tf32(addr[1], v.y);
                sts_tf32(addr[2], v.z); sts_tf32(addr[3], v.w);
            }
            n += 4; g += 384;
            #pragma unroll
            for (int e = 0; e < 4; e++) { addr[e] += dlt[e]; dlt[e] = 18432 - dlt[e]; }
        }
    }
    // ---- stage d: thread owns (i0 = tid/48, rem); 4 steps of +8 samples ----
    {
        const int i0  = tid / 48;                    // 0..7
        const int rem = tid - 48 * i0;
        int addr[4];
        #pragma unroll
        for (int e = 0; e < 4; e++) {
            int f = 4 * rem + e;                     // 0..191 within d row [32c][6s]
            int c = f / 6, s = f - 6 * c;
            int w = 3 * c + 2;
            int r = 6 * i0 + s;
            addr[e] = (int)sb + A_OFF + 4 * a_word(r, w);
        }
        const float4* d4 = (const float4*)dd;
        int g = (n0 + i0) * 48 + rem;
        int n = n0 + i0;
        #pragma unroll
        for (int st = 0; st < 4; st++) {
            if (n < nsamp) {
                float4 v = d4[g];
                sts_tf32(addr[0], v.x); sts_tf32(addr[1], v.y);
                sts_tf32(addr[2], v.z); sts_tf32(addr[3], v.w);
            }
            n += 8; g += 384;                        // r += 48 -> constant +18432 B
            #pragma unroll
            for (int e = 0; e < 4; e++) addr[e] += 18432;
        }
    }
    __syncthreads();

    // ---- compute: warp wid = mtile (16 rows), all 32 outputs ----
    const int wid  = tid >> 5, lane = tid & 31;
    const int g8   = lane >> 2, t4 = lane & 3;

    float acc[NNT][4];
    #pragma unroll
    for (int nt = 0; nt < NNT; nt++) {               // bias init (c0/c2 share col 2t, c1/c3 col 2t+1)
        float2 bb = *(const float2*)(smem + BIAS_OFF + (nt * 8 + 2 * t4) * 4);
        acc[nt][0] = bb.x; acc[nt][1] = bb.y; acc[nt][2] = bb.x; acc[nt][3] = bb.y;
    }

    const char* abase = smem + A_OFF + wid * (NKT * 512) + lane * 16;
    const char* bbase = smem + B_OFF + lane * 8;
    #pragma unroll
    for (int kt = 0; kt < NKT; kt++) {
        uint4 av = *(const uint4*)(abase + kt * 512);
        #pragma unroll
        for (int nt = 0; nt < NNT; nt++) {
            uint2 bv = *(const uint2*)(bbase + (kt * NNT + nt) * 256);
            asm volatile(
                "mma.sync.aligned.m16n8k8.row.col.f32.tf32.tf32.f32 "
                "{%0,%1,%2,%3}, {%4,%5,%6,%7}, {%8,%9}, {%0,%1,%2,%3};"
                : "+f"(acc[nt][0]), "+f"(acc[nt][1]), "+f"(acc[nt][2]), "+f"(acc[nt][3])
                : "r"(av.x), "r"(av.y), "r"(av.z), "r"(av.w), "r"(bv.x), "r"(bv.y));
        }
    }

    // ---- epilogue: c0,c1 -> row g8; c2,c3 -> row g8+8 ----
    {
        int j_lo = j0 + wid * 16 + g8;
        int j_hi = j_lo + 8;
        int jmax = nsamp * 6;
        int n_lo = j_lo / 6, s_lo = j_lo - 6 * n_lo;
        int n_hi = j_hi / 6, s_hi = j_hi - 6 * n_hi;
        float* plo = out + (size_t)n_lo * 192 + s_lo;
        float* phi = out + (size_t)n_hi * 192 + s_hi;
        #pragma unroll
        for (int nt = 0; nt < NNT; nt++) {
            int o = nt * 8 + 2 * t4;
            if (j_lo < jmax) {
                plo[o * 6]       = acc[nt][0];
                plo[(o + 1) * 6] = acc[nt][1];
            }
            if (j_hi < jmax) {
                phi[o * 6]       = acc[nt][2];
                phi[(o + 1) * 6] = acc[nt][3];
            }
        }
    }
}

extern "C" void kernel_launch(void* const* d_in, const int* in_sizes, int n_in,
                              void* d_out, int out_size) {
    const float* x = (const float*)d_in[0];
    const float* d = (const float*)d_in[1];
    const float* W = (const float*)d_in[2];
    const float* b = (const float*)d_in[3];
    float* out = (float*)d_out;

    int nsamp = in_sizes[0] / 384;

    cudaFuncSetAttribute(dijet_mma, cudaFuncAttributeMaxDynamicSharedMemorySize, SMEM_TOTAL);
    prep_WF<<<24, 128>>>(W);
    int nblk = (nsamp * 6 + ROWS - 1) / ROWS;
    dijet_mma<<<nblk, THREADS, SMEM_TOTAL>>>(x, d, b, out, nsamp);
}

// round 8
// speedup vs baseline: 3.3372x; 1.1215x over previous
#include <cuda_runtime.h>
#include <cstdint>

// out[n,o,s] = sum_k din[j,k] * W[o,k] + b[o],  j = n*6+s, K=96 (k = 3c+tap)
// din[j,3c+0]=x[n,c,2s], din[j,3c+1]=x[n,c,2s+1], din[j,3c+2]=d[n,c,s]
// mma.sync.m16n8k8.row.col.f32.tf32.tf32.f32 (plain PTX, compute_103-safe).
//
// A tile layout (XOR-swizzled fragment order), value (row r, ktile kt, col t in 0..7):
//   group = (t&3) ^ ((r>>1)&3)              (spreads q-sharing lanes across banks)
//   idx   = ((t>>2)<<1 | ((r>>3)&1)) ^ (kt&3)   (spreads c>>2 across bank bits 1:0)
//   word  = (r>>4)*1536 + kt*128 + (r&7)*16 + group*4 + idx
// Column assignment: x-taps: kt=c>>2, t=(c&3)+4*par.  d-tap: kt=8+(c>>3), t=c&7.
// Compute lane (g8,t4): its 4 words are contiguous at group (t4 ^ ((g8>>1)&3));
// mma operands a_i = word[i ^ (kt&3)]  (compile-time permutation per kt).

#define ROWS 192
#define THREADS 384
#define A_OFF 0
#define A_BYTES (ROWS * 96 * 4)            // 73728
#define B_OFF A_BYTES
#define B_BYTES 12288
#define BIAS_OFF (B_OFF + B_BYTES)
#define SMEM_TOTAL (BIAS_OFF + 128)        // 86144 -> 2 CTAs/SM
#define EPI_STRIDE 200                     // words per sample in epilogue region

__device__ __align__(16) float WF_g[3072];

__global__ void prep_WF(const float* __restrict__ W) {
    int t = blockIdx.x * blockDim.x + threadIdx.x;
    if (t < 3072) {
        int o = t / 96, k = t - 96 * o;
        int c = k / 3, tap = k - 3 * c;
        int kt, tc;
        if (tap < 2) { kt = c >> 2;       tc = (c & 3) + 4 * tap; }
        else         { kt = 8 + (c >> 3); tc = c & 7; }
        uint32_t v;
        asm("cvt.rna.tf32.f32 %0, %1;" : "=r"(v) : "f"(W[t]));
        int word = (kt * 4 + (o >> 3)) * 64 + ((o & 7) * 4 + (tc & 3)) * 2 + (tc >> 2);
        WF_g[word] = __uint_as_float(v);
    }
}

static __device__ __forceinline__ uint32_t smem_u32(const void* p) {
    uint32_t a;
    asm("{ .reg .u64 t; cvta.to.shared.u64 t, %1; cvt.u32.u64 %0, t; }" : "=r"(a) : "l"(p));
    return a;
}
static __device__ __forceinline__ void sts_tf32(int addr, float v) {
    uint32_t t;
    asm("cvt.rna.tf32.f32 %0, %1;" : "=r"(t) : "f"(v));
    asm volatile("st.shared.b32 [%0], %1;" :: "r"(addr), "r"(t));
}
static __device__ __forceinline__ void mma4(float* a, uint32_t a0, uint32_t a1,
                                            uint32_t a2, uint32_t a3, uint2 bv) {
    asm volatile(
        "mma.sync.aligned.m16n8k8.row.col.f32.tf32.tf32.f32 "
        "{%0,%1,%2,%3}, {%4,%5,%6,%7}, {%8,%9}, {%0,%1,%2,%3};"
        : "+f"(a[0]), "+f"(a[1]), "+f"(a[2]), "+f"(a[3])
        : "r"(a0), "r"(a1), "r"(a2), "r"(a3), "r"(bv.x), "r"(bv.y));
}

// x-stage address for value (local row r, channel c, parity par)
static __device__ __forceinline__ int a_word_x(int r, int c, int par) {
    int kt = c >> 2;
    int group = (c & 3) ^ ((r >> 1) & 3);
    int idx = ((par << 1) | ((r >> 3) & 1)) ^ (kt & 3);
    return (r >> 4) * 1536 + kt * 128 + (r & 7) * 16 + group * 4 + idx;
}
static __device__ __forceinline__ int a_word_d(int r, int c) {
    int kt = 8 + (c >> 3);
    int group = (c & 3) ^ ((r >> 1) & 3);
    int idx = ((((c >> 2) & 1) << 1) | ((r >> 3) & 1)) ^ (kt & 3);
    return (r >> 4) * 1536 + kt * 128 + (r & 7) * 16 + group * 4 + idx;
}

__global__ void __launch_bounds__(THREADS, 2)
dijet_mma(const float* __restrict__ x, const float* __restrict__ dd,
          const float* __restrict__ bvec, float* __restrict__ out, int nsamp)
{
    extern __shared__ char smem[];
    const uint32_t sb = smem_u32(smem);
    const int tid = threadIdx.x;
    const int j0  = blockIdx.x * ROWS;
    const int n0  = j0 / 6;

    // ---- stage B (pre-packed) + bias ----
    {
        const float4* wf4 = (const float4*)WF_g;
        float4* b4 = (float4*)(smem + B_OFF);
        #pragma unroll
        for (int t = tid; t < B_BYTES / 16; t += THREADS) b4[t] = wf4[t];
        if (tid < 32) ((float*)(smem + BIAS_OFF))[tid] = bvec[tid];
    }

    // ---- stage x: thread owns (i0=tid/96, rem); 8 steps of +4 samples ----
    {
        const int i0  = tid / 96;
        const int rem = tid - 96 * i0;
        const int c   = rem / 3, qq = rem - 3 * c;
        int addr[4], dlt[4];
        #pragma unroll
        for (int e = 0; e < 4; e++) {
            int par = e & 1;
            int s   = 2 * qq + (e >> 1);
            int r   = 6 * i0 + s;
            int w   = a_word_x(r, c, par);
            addr[e] = (int)sb + A_OFF + 4 * w;
            int h0  = (r >> 3) & 1;
            int b0  = w & 1;                       // current idx bit0
            dlt[e]  = 6144 * (1 + h0) + 4 * (1 - 2 * b0);
        }
        const float4* x4 = (const float4*)x;
        int g = (n0 + i0) * 96 + rem;
        int n = n0 + i0;
        #pragma unroll
        for (int st = 0; st < 8; st++) {
            if (n < nsamp) {
                float4 v = x4[g];
                sts_tf32(addr[0], v.x); sts_tf32(addr[1], v.y);
                sts_tf32(addr[2], v.z); sts_tf32(addr[3], v.w);
            }
            n += 4; g += 384;
            #pragma unroll
            for (int e = 0; e < 4; e++) { addr[e] += dlt[e]; dlt[e] = 18432 - dlt[e]; }
        }
    }
    // ---- stage d: thread owns (i0=tid/48, rem); 4 steps of +8 samples ----
    {
        const int i0  = tid / 48;
        const int rem = tid - 48 * i0;
        int addr[4];
        #pragma unroll
        for (int e = 0; e < 4; e++) {
            int f = 4 * rem + e;
            int c = f / 6, s = f - 6 * c;
            int r = 6 * i0 + s;
            addr[e] = (int)sb + A_OFF + 4 * a_word_d(r, c);
        }
        const float4* d4 = (const float4*)dd;
        int g = (n0 + i0) * 48 + rem;
        int n = n0 + i0;
        #pragma unroll
        for (int st = 0; st < 4; st++) {
            if (n < nsamp) {
                float4 v = d4[g];
                sts_tf32(addr[0], v.x); sts_tf32(addr[1], v.y);
                sts_tf32(addr[2], v.z); sts_tf32(addr[3], v.w);
            }
            n += 8; g += 384;
            #pragma unroll
            for (int e = 0; e < 4; e++) addr[e] += 18432;
        }
    }
    __syncthreads();

    // ---- compute: warps 0-5, each owns mtiles (2w, 2w+1) x all 4 ntiles ----
    const int wid = tid >> 5, lane = tid & 31;
    const int g8 = lane >> 2, t4 = lane & 3;

    float acc0[4][4], acc1[4][4];

    if (wid < 6) {
        #pragma unroll
        for (int nt = 0; nt < 4; nt++) {
            float2 bb = *(const float2*)(smem + BIAS_OFF + (nt * 8 + 2 * t4) * 4);
            acc0[nt][0] = bb.x; acc0[nt][1] = bb.y; acc0[nt][2] = bb.x; acc0[nt][3] = bb.y;
            acc1[nt][0] = bb.x; acc1[nt][1] = bb.y; acc1[nt][2] = bb.x; acc1[nt][3] = bb.y;
        }
        const int aoff = g8 * 64 + ((t4 ^ ((g8 >> 1) & 3)) << 4);
        const char* a0base = smem + A_OFF + (2 * wid)     * 6144 + aoff;
        const char* a1base = smem + A_OFF + (2 * wid + 1) * 6144 + aoff;
        const char* bbase  = smem + B_OFF + lane * 8;

#define KSTEP(KT, RHO) { \
        uint4 av0 = *(const uint4*)(a0base + (KT) * 512); \
        uint4 av1 = *(const uint4*)(a1base + (KT) * 512); \
        uint32_t p0[4] = {av0.x, av0.y, av0.z, av0.w}; \
        uint32_t p1[4] = {av1.x, av1.y, av1.z, av1.w}; \
        _Pragma("unroll") \
        for (int nt = 0; nt < 4; nt++) { \
            uint2 bv = *(const uint2*)(bbase + ((KT) * 4 + nt) * 256); \
            mma4(acc0[nt], p0[0 ^ (RHO)], p0[1 ^ (RHO)], p0[2 ^ (RHO)], p0[3 ^ (RHO)], bv); \
            mma4(acc1[nt], p1[0 ^ (RHO)], p1[1 ^ (RHO)], p1[2 ^ (RHO)], p1[3 ^ (RHO)], bv); \
        } }

        KSTEP(0, 0) KSTEP(1, 1) KSTEP(2, 2) KSTEP(3, 3)
        KSTEP(4, 0) KSTEP(5, 1) KSTEP(6, 2) KSTEP(7, 3)
        KSTEP(8, 0) KSTEP(9, 1) KSTEP(10, 2) KSTEP(11, 3)
#undef KSTEP
    }

    // ---- epilogue: compute warps scatter to smem (stride-200), all warps copy out ----
    __syncthreads();
    if (wid < 6) {
        float* ep = (float*)smem;
        #pragma unroll
        for (int mt = 0; mt < 2; mt++) {
            const float (*ac)[4] = mt ? acc1 : acc0;
            #pragma unroll
            for (int h = 0; h < 2; h++) {
                int r = (2 * wid + mt) * 16 + g8 + 8 * h;
                int i = r / 6, s = r - 6 * i;
                int base = i * EPI_STRIDE + s;
                #pragma unroll
                for (int nt = 0; nt < 4; nt++) {
                    int o = nt * 8 + 2 * t4;
                    ep[base + o * 6]       = ac[nt][2 * h];
                    ep[base + (o + 1) * 6] = ac[nt][2 * h + 1];
                }
            }
        }
    }
    __syncthreads();
    {
        int nloc = min(nsamp - n0, 32);
        int limit = nloc * 192;
        const float* ep = (const float*)smem;
        float* ob = out + (size_t)n0 * 192;
        #pragma unroll
        for (int it = 0; it < 4; it++) {
            int u = it * 1536 + tid * 4;
            if (u < limit) {
                int i = u / 192, m = u - 192 * i;
                float4 v = *(const float4*)(ep + i * EPI_STRIDE + m);
                *(float4*)(ob + u) = v;
            }
        }
    }
}

extern "C" void kernel_launch(void* const* d_in, const int* in_sizes, int n_in,
                              void* d_out, int out_size) {
    const float* x = (const float*)d_in[0];
    const float* d = (const float*)d_in[1];
    const float* W = (const float*)d_in[2];
    const float* b = (const float*)d_in[3];
    float* out = (float*)d_out;

    int nsamp = in_sizes[0] / 384;

    cudaFuncSetAttribute(dijet_mma, cudaFuncAttributeMaxDynamicSharedMemorySize, SMEM_TOTAL);
    prep_WF<<<24, 128>>>(W);
    int nblk = (nsamp * 6 + ROWS - 1) / ROWS;
    dijet_mma<<<nblk, THREADS, SMEM_TOTAL>>>(x, d, b, out, nsamp);
}